// round 1
// baseline (speedup 1.0000x reference)
#include <cuda_runtime.h>

#define NN  100000
#define EIN 1600000
#define ECN 800000
#define GN  2000
#define FDIM 512
#define CC  128

// -------- scratch (device globals; no allocation) --------
__device__ float g_h[NN*CC];
__device__ float g_xw[NN*CC];
__device__ float g_f[NN*CC];
__device__ float g_agg[NN*CC];
__device__ float g_hc[NN*CC];
__device__ float g_z[NN*CC];
__device__ float g_el[NN*4];
__device__ float g_er[NN*4];
__device__ float g_emax[NN*4];
__device__ float g_esum[NN*4];
__device__ float g_eexp[ECN*4];
__device__ float g_iso[NN];
__device__ float g_isi[NN];
__device__ float g_att[NN];
__device__ float g_gsum[GN*CC];
__device__ float g_gcnt[GN];
__device__ float g_bnsum[CC];
__device__ float g_bnsq[CC];
__device__ float g_bnscale[CC];
__device__ float g_bnshift[CC];

__device__ __forceinline__ float leakyr(float x) { return x >= 0.f ? x : 0.2f * x; }

__device__ __forceinline__ void atomicMaxF(float* addr, float val) {
    int* ai = (int*)addr;
    int old = *ai;
    while (val > __int_as_float(old)) {
        int assumed = old;
        old = atomicCAS(ai, assumed, __float_as_int(val));
        if (old == assumed) break;
    }
}

// -------- utility --------
__global__ void fill_kernel(float* p, float v, int n) {
    int i = blockIdx.x * blockDim.x + threadIdx.x;
    if (i < n) p[i] = v;
}

__global__ void deg_kernel(const int* __restrict__ src, const int* __restrict__ dst,
                           float* dout, float* din) {
    int e = blockIdx.x * blockDim.x + threadIdx.x;
    if (e >= EIN) return;
    atomicAdd(&dout[src[e]], 1.f);
    atomicAdd(&din[dst[e]], 1.f);
}

__global__ void invsqrt_kernel(float* p, int n) {
    int i = blockIdx.x * blockDim.x + threadIdx.x;
    if (i < n) p[i] = rsqrtf(fmaxf(p[i], 1.f));
}

// -------- SGEMM: C[M,128] = A[M,K] @ W[K,128], optional per-row scale --------
__global__ __launch_bounds__(256) void sgemm128(
    const float* __restrict__ A, const float* __restrict__ W,
    float* __restrict__ Cmat, const float* __restrict__ rowscale, int M, int K)
{
    __shared__ float As[16][64];
    __shared__ float Ws[16][128];
    int tid = threadIdx.x;
    int tx = tid & 31;        // col group: cols tx*4..tx*4+3
    int ty = tid >> 5;        // row group: rows ty*8..ty*8+7
    int row0 = blockIdx.x * 64;

    float acc[8][4];
#pragma unroll
    for (int i = 0; i < 8; i++)
#pragma unroll
        for (int j = 0; j < 4; j++) acc[i][j] = 0.f;

    int lm = tid >> 2;          // 0..63  A tile row
    int lk = (tid & 3) * 4;     // 0,4,8,12
    int wk = tid >> 4;          // 0..15  W tile row
    int wc = (tid & 15) * 8;    // 0..120

    for (int k0 = 0; k0 < K; k0 += 16) {
        float4 av = make_float4(0.f, 0.f, 0.f, 0.f);
        int arow = row0 + lm;
        if (arow < M) av = *(const float4*)(A + (size_t)arow * K + k0 + lk);
        As[lk + 0][lm] = av.x; As[lk + 1][lm] = av.y;
        As[lk + 2][lm] = av.z; As[lk + 3][lm] = av.w;

        float4 w0 = *(const float4*)(W + (size_t)(k0 + wk) * 128 + wc);
        float4 w1 = *(const float4*)(W + (size_t)(k0 + wk) * 128 + wc + 4);
        *(float4*)&Ws[wk][wc] = w0;
        *(float4*)&Ws[wk][wc + 4] = w1;
        __syncthreads();

#pragma unroll
        for (int kk = 0; kk < 16; kk++) {
            float4 b = *(const float4*)&Ws[kk][tx * 4];
            float4 aA = *(const float4*)&As[kk][ty * 8];
            float4 aB = *(const float4*)&As[kk][ty * 8 + 4];
            float a0[8] = {aA.x, aA.y, aA.z, aA.w, aB.x, aB.y, aB.z, aB.w};
#pragma unroll
            for (int i = 0; i < 8; i++) {
                acc[i][0] += a0[i] * b.x;
                acc[i][1] += a0[i] * b.y;
                acc[i][2] += a0[i] * b.z;
                acc[i][3] += a0[i] * b.w;
            }
        }
        __syncthreads();
    }

#pragma unroll
    for (int i = 0; i < 8; i++) {
        int r = row0 + ty * 8 + i;
        if (r < M) {
            float s = rowscale ? rowscale[r] : 1.f;
            float4 o = make_float4(acc[i][0] * s, acc[i][1] * s, acc[i][2] * s, acc[i][3] * s);
            *(float4*)(Cmat + (size_t)r * 128 + tx * 4) = o;
        }
    }
}

// -------- GAT attention dot products: el/er per (node, head) --------
__global__ void elr_kernel(const float* __restrict__ f, const float* __restrict__ al,
                           const float* __restrict__ ar, float* __restrict__ el,
                           float* __restrict__ er, int H)
{
    int warp = (blockIdx.x * blockDim.x + threadIdx.x) >> 5;
    if (warp >= NN) return;
    int lane = threadIdx.x & 31;
    float4 fv = ((const float4*)f)[(size_t)warp * 32 + lane];
    float4 a = ((const float4*)al)[lane];
    float4 b = ((const float4*)ar)[lane];
    float pl = fv.x * a.x + fv.y * a.y + fv.z * a.z + fv.w * a.w;
    float pr = fv.x * b.x + fv.y * b.y + fv.z * b.z + fv.w * b.w;
    int L = 32 / H;  // lanes per head
    for (int off = L >> 1; off; off >>= 1) {
        pl += __shfl_down_sync(0xffffffffu, pl, off);
        pr += __shfl_down_sync(0xffffffffu, pr, off);
    }
    if ((lane & (L - 1)) == 0) {
        int h = lane / L;
        el[warp * H + h] = pl;
        er[warp * H + h] = pr;
    }
}

// -------- GraphConv scatter: warp per edge --------
__global__ void gc_scatter(const float* __restrict__ xw, const int* __restrict__ src,
                           const int* __restrict__ dst, float* __restrict__ agg)
{
    int e = (blockIdx.x * blockDim.x + threadIdx.x) >> 5;
    if (e >= EIN) return;
    int lane = threadIdx.x & 31;
    int s = src[e], d = dst[e];
    float4 v = ((const float4*)xw)[(size_t)s * 32 + lane];
    float* ap = agg + (size_t)d * 128 + lane * 4;
    atomicAdd(ap + 0, v.x);
    atomicAdd(ap + 1, v.y);
    atomicAdd(ap + 2, v.z);
    atomicAdd(ap + 3, v.w);
}

// -------- GAT edge softmax passes --------
__global__ void gat_max(const int* __restrict__ src, const int* __restrict__ dst,
                        const float* __restrict__ el, const float* __restrict__ er,
                        float* emax, int H)
{
    int t = blockIdx.x * blockDim.x + threadIdx.x;
    if (t >= ECN * H) return;
    int e = t / H, h = t - e * H;
    int d = dst[e];
    float v = leakyr(el[src[e] * H + h] + er[d * H + h]);
    atomicMaxF(&emax[d * H + h], v);
}

__global__ void gat_exp(const int* __restrict__ src, const int* __restrict__ dst,
                        const float* __restrict__ el, const float* __restrict__ er,
                        const float* __restrict__ emax, float* esum, float* eexp, int H)
{
    int t = blockIdx.x * blockDim.x + threadIdx.x;
    if (t >= ECN * H) return;
    int e = t / H, h = t - e * H;
    int d = dst[e];
    float v = leakyr(el[src[e] * H + h] + er[d * H + h]);
    float ex = __expf(v - emax[d * H + h]);
    eexp[t] = ex;
    atomicAdd(&esum[d * H + h], ex);
}

__global__ void gat_agg(const float* __restrict__ f, const int* __restrict__ src,
                        const int* __restrict__ dst, const float* __restrict__ eexp,
                        const float* __restrict__ esum, float* __restrict__ hc, int H)
{
    int e = (blockIdx.x * blockDim.x + threadIdx.x) >> 5;
    if (e >= ECN) return;
    int lane = threadIdx.x & 31;
    int s = src[e], d = dst[e];
    int h = (lane * H) >> 5;  // = lane / (32/H)
    float alpha = eexp[e * H + h] / esum[d * H + h];
    float4 v = ((const float4*)f)[(size_t)s * 32 + lane];
    float* hp = hc + (size_t)d * 128 + lane * 4;
    atomicAdd(hp + 0, alpha * v.x);
    atomicAdd(hp + 1, alpha * v.y);
    atomicAdd(hp + 2, alpha * v.z);
    atomicAdd(hp + 3, alpha * v.w);
}

// layer-3 attention sums over SOURCE nodes
__global__ void att_kernel(const int* __restrict__ src, const int* __restrict__ dst,
                           const float* __restrict__ eexp, const float* __restrict__ esum,
                           float* att)
{
    int e = blockIdx.x * blockDim.x + threadIdx.x;
    if (e >= ECN) return;
    float alpha = eexp[e] / esum[dst[e]];
    atomicAdd(&att[src[e]], alpha);
}

// -------- combine (+ optional leaky) + BN statistics --------
__global__ __launch_bounds__(256) void combine_kernel(
    const float* __restrict__ agg, const float* __restrict__ hc,
    const float* __restrict__ isi, const float* __restrict__ bgc,
    const float* __restrict__ bgat, float* __restrict__ z,
    float* bnsum, float* bnsq, int do_leaky)
{
    __shared__ float ssum[256], ssq[256];
    int tidx = threadIdx.x;
    int stride = gridDim.x * 256;
    float ls = 0.f, lq = 0.f;
    for (int idx = blockIdx.x * 256 + tidx; idx < NN * 128; idx += stride) {
        int n = idx >> 7, ch = idx & 127;
        float v = agg[idx] * isi[n] + bgc[ch] + hc[idx] + bgat[ch];
        if (do_leaky) v = leakyr(v);
        z[idx] = v;
        ls += v;
        lq += v * v;
    }
    ssum[tidx] = ls; ssq[tidx] = lq;
    __syncthreads();
    if (tidx < 128) {
        atomicAdd(&bnsum[tidx], ssum[tidx] + ssum[tidx + 128]);
        atomicAdd(&bnsq[tidx], ssq[tidx] + ssq[tidx + 128]);
    }
}

__global__ void bn_prep(const float* bnsum, const float* bnsq, const float* __restrict__ g,
                        const float* __restrict__ be, float* scale, float* shift)
{
    int c = threadIdx.x;
    if (c >= CC) return;
    float mu = bnsum[c] / (float)NN;
    float var = bnsq[c] / (float)NN - mu * mu;
    float sc = g[c] * rsqrtf(var + 1e-5f);
    scale[c] = sc;
    shift[c] = be[c] - mu * sc;
}

__global__ void bn_apply(const float* __restrict__ z, const float* __restrict__ scale,
                         const float* __restrict__ shift, float* __restrict__ h)
{
    int idx = blockIdx.x * blockDim.x + threadIdx.x;
    if (idx >= NN * 128) return;
    int ch = idx & 127;
    h[idx] = z[idx] * scale[ch] + shift[ch];
}

// -------- pooling --------
__global__ void gcnt_kernel(const int* __restrict__ gid, float* gcnt) {
    int n = blockIdx.x * blockDim.x + threadIdx.x;
    if (n < NN) atomicAdd(&gcnt[gid[n]], 1.f);
}

__global__ void pool_kernel(const float* __restrict__ h, const float* __restrict__ att,
                            const int* __restrict__ gid, float* gsum)
{
    int idx = blockIdx.x * blockDim.x + threadIdx.x;
    if (idx >= NN * 128) return;
    int n = idx >> 7, ch = idx & 127;
    atomicAdd(&gsum[gid[n] * 128 + ch], h[idx] * att[n]);
}

__global__ void out_kernel(const float* __restrict__ gsum, const float* __restrict__ gcnt,
                           const float* __restrict__ att, float* __restrict__ out)
{
    int i = blockIdx.x * blockDim.x + threadIdx.x;
    if (i < GN * 128) {
        out[i] = gsum[i] / fmaxf(gcnt[i >> 7], 1.f);
    } else if (i < GN * 128 + NN) {
        out[i] = att[i - GN * 128];
    }
}

static inline int cdiv(int a, int b) { return (a + b - 1) / b; }

extern "C" void kernel_launch(void* const* d_in, const int* in_sizes, int n_in,
                              void* d_out, int out_size)
{
    (void)in_sizes; (void)n_in; (void)out_size;
    const float* feat = (const float*)d_in[0];
    const int* isrc = (const int*)d_in[1];
    const int* idst = (const int*)d_in[2];
    const int* csrc = (const int*)d_in[3];
    const int* cdst = (const int*)d_in[4];
    const int* gid  = (const int*)d_in[5];
    const float* Wgc[3]  = {(const float*)d_in[6],  (const float*)d_in[12], (const float*)d_in[18]};
    const float* bgc[3]  = {(const float*)d_in[7],  (const float*)d_in[13], (const float*)d_in[19]};
    const float* Wgat[3] = {(const float*)d_in[8],  (const float*)d_in[14], (const float*)d_in[20]};
    const float* al[3]   = {(const float*)d_in[9],  (const float*)d_in[15], (const float*)d_in[21]};
    const float* ar[3]   = {(const float*)d_in[10], (const float*)d_in[16], (const float*)d_in[22]};
    const float* bga[3]  = {(const float*)d_in[11], (const float*)d_in[17], (const float*)d_in[23]};
    const float* gam[3]  = {(const float*)d_in[24], (const float*)d_in[26], (const float*)d_in[28]};
    const float* bet[3]  = {(const float*)d_in[25], (const float*)d_in[27], (const float*)d_in[29]};
    float* out = (float*)d_out;

    float *h, *xw, *f, *agg, *hc, *z, *el, *er, *emax, *esum, *eexp;
    float *iso, *isi, *att, *gsum, *gcnt, *bnsum, *bnsq, *bnscale, *bnshift;
    cudaGetSymbolAddress((void**)&h, g_h);
    cudaGetSymbolAddress((void**)&xw, g_xw);
    cudaGetSymbolAddress((void**)&f, g_f);
    cudaGetSymbolAddress((void**)&agg, g_agg);
    cudaGetSymbolAddress((void**)&hc, g_hc);
    cudaGetSymbolAddress((void**)&z, g_z);
    cudaGetSymbolAddress((void**)&el, g_el);
    cudaGetSymbolAddress((void**)&er, g_er);
    cudaGetSymbolAddress((void**)&emax, g_emax);
    cudaGetSymbolAddress((void**)&esum, g_esum);
    cudaGetSymbolAddress((void**)&eexp, g_eexp);
    cudaGetSymbolAddress((void**)&iso, g_iso);
    cudaGetSymbolAddress((void**)&isi, g_isi);
    cudaGetSymbolAddress((void**)&att, g_att);
    cudaGetSymbolAddress((void**)&gsum, g_gsum);
    cudaGetSymbolAddress((void**)&gcnt, g_gcnt);
    cudaGetSymbolAddress((void**)&bnsum, g_bnsum);
    cudaGetSymbolAddress((void**)&bnsq, g_bnsq);
    cudaGetSymbolAddress((void**)&bnscale, g_bnscale);
    cudaGetSymbolAddress((void**)&bnshift, g_bnshift);

    // ---- degrees (inv-sqrt, clamped to >=1) ----
    fill_kernel<<<cdiv(NN, 256), 256>>>(iso, 0.f, NN);
    fill_kernel<<<cdiv(NN, 256), 256>>>(isi, 0.f, NN);
    deg_kernel<<<cdiv(EIN, 256), 256>>>(isrc, idst, iso, isi);
    invsqrt_kernel<<<cdiv(NN, 256), 256>>>(iso, NN);
    invsqrt_kernel<<<cdiv(NN, 256), 256>>>(isi, NN);

    const int Hs[3] = {4, 4, 1};
    for (int L = 0; L < 3; L++) {
        const float* A = (L == 0) ? feat : h;
        int K = (L == 0) ? FDIM : CC;
        int H = Hs[L];

        fill_kernel<<<cdiv(NN * CC, 256), 256>>>(agg, 0.f, NN * CC);
        fill_kernel<<<cdiv(NN * CC, 256), 256>>>(hc, 0.f, NN * CC);
        fill_kernel<<<cdiv(NN * H, 256), 256>>>(esum, 0.f, NN * H);
        fill_kernel<<<cdiv(NN * H, 256), 256>>>(emax, -1e30f, NN * H);
        fill_kernel<<<1, 128>>>(bnsum, 0.f, CC);
        fill_kernel<<<1, 128>>>(bnsq, 0.f, CC);

        sgemm128<<<cdiv(NN, 64), 256>>>(A, Wgc[L], xw, iso, NN, K);
        sgemm128<<<cdiv(NN, 64), 256>>>(A, Wgat[L], f, nullptr, NN, K);

        elr_kernel<<<cdiv(NN * 32, 128), 128>>>(f, al[L], ar[L], el, er, H);

        gc_scatter<<<cdiv(EIN * 32, 256), 256>>>(xw, isrc, idst, agg);

        gat_max<<<cdiv(ECN * H, 256), 256>>>(csrc, cdst, el, er, emax, H);
        gat_exp<<<cdiv(ECN * H, 256), 256>>>(csrc, cdst, el, er, emax, esum, eexp, H);
        gat_agg<<<cdiv(ECN * 32, 256), 256>>>(f, csrc, cdst, eexp, esum, hc, H);

        if (L == 2) {
            fill_kernel<<<cdiv(NN, 256), 256>>>(att, 0.f, NN);
            att_kernel<<<cdiv(ECN, 256), 256>>>(csrc, cdst, eexp, esum, att);
        }

        combine_kernel<<<2048, 256>>>(agg, hc, isi, bgc[L], bga[L], z, bnsum, bnsq, (L < 2) ? 1 : 0);
        bn_prep<<<1, 128>>>(bnsum, bnsq, gam[L], bet[L], bnscale, bnshift);
        bn_apply<<<cdiv(NN * CC, 256), 256>>>(z, bnscale, bnshift, h);
    }

    // ---- pooling ----
    fill_kernel<<<cdiv(GN * CC, 256), 256>>>(gsum, 0.f, GN * CC);
    fill_kernel<<<cdiv(GN, 256), 256>>>(gcnt, 0.f, GN);
    gcnt_kernel<<<cdiv(NN, 256), 256>>>(gid, gcnt);
    pool_kernel<<<cdiv(NN * CC, 256), 256>>>(h, att, gid, gsum);
    out_kernel<<<cdiv(GN * CC + NN, 256), 256>>>(gsum, gcnt, att, out);
}

// round 2
// speedup vs baseline: 2.6886x; 2.6886x over previous
#include <cuda_runtime.h>
#include <cstdint>

#define NN  100000
#define EIN 1600000
#define ECN 800000
#define GN  2000
#define FDIM 512
#define CC  128

// -------- scratch (device globals; no allocation) --------
__device__ float g_h[NN*CC];
__device__ float g_xw[NN*CC];
__device__ float g_f[NN*CC];
__device__ float g_agg[NN*CC];
__device__ float g_hc[NN*CC];
__device__ float g_z[NN*CC];
__device__ float g_el[NN*4];
__device__ float g_er[NN*4];
__device__ float g_emax[NN*4];
__device__ float g_esum[NN*4];
__device__ float g_eexp[ECN*4];
__device__ float g_iso[NN];
__device__ float g_isi[NN];
__device__ float g_att[NN];
__device__ float g_gsum[GN*CC];
__device__ float g_gcnt[GN];
__device__ float g_bnsum[CC];
__device__ float g_bnsq[CC];
__device__ float g_bnscale[CC];
__device__ float g_bnshift[CC];

__device__ __forceinline__ float leakyr(float x) { return x >= 0.f ? x : 0.2f * x; }

__device__ __forceinline__ void atomicMaxF(float* addr, float val) {
    int* ai = (int*)addr;
    int old = *ai;
    while (val > __int_as_float(old)) {
        int assumed = old;
        old = atomicCAS(ai, assumed, __float_as_int(val));
        if (old == assumed) break;
    }
}

__device__ __forceinline__ void red4(float* p, float x, float y, float z, float w) {
    asm volatile("red.global.add.v4.f32 [%0], {%1,%2,%3,%4};"
                 :: "l"(p), "f"(x), "f"(y), "f"(z), "f"(w) : "memory");
}

__device__ __forceinline__ float to_tf32(float x) {
    float r;
    asm("cvt.rna.tf32.f32 %0, %1;" : "=f"(r) : "f"(x));
    return r;
}

__device__ __forceinline__ void mma_tf32(float* d, const uint32_t* a, const uint32_t* b) {
    asm volatile(
        "mma.sync.aligned.m16n8k8.row.col.f32.tf32.tf32.f32 "
        "{%0,%1,%2,%3}, {%4,%5,%6,%7}, {%8,%9}, {%0,%1,%2,%3};"
        : "+f"(d[0]), "+f"(d[1]), "+f"(d[2]), "+f"(d[3])
        : "r"(a[0]), "r"(a[1]), "r"(a[2]), "r"(a[3]), "r"(b[0]), "r"(b[1]));
}

// -------- utility --------
__global__ void fill_kernel(float* p, float v, int n) {
    int i = blockIdx.x * blockDim.x + threadIdx.x;
    if (i < n) p[i] = v;
}

__global__ void deg_kernel(const int* __restrict__ src, const int* __restrict__ dst,
                           float* dout, float* din) {
    int e = blockIdx.x * blockDim.x + threadIdx.x;
    if (e >= EIN) return;
    atomicAdd(&dout[src[e]], 1.f);
    atomicAdd(&din[dst[e]], 1.f);
}

__global__ void invsqrt_kernel(float* p, int n) {
    int i = blockIdx.x * blockDim.x + threadIdx.x;
    if (i < n) p[i] = rsqrtf(fmaxf(p[i], 1.f));
}

// ===================================================================
// Fused dual-GEMM (tf32 tensor core):
//   Ca[M,128] = (affine(A) @ Wa) * rowscale   Cb[M,128] = affine(A) @ Wb
//   A: [M,K] fp32; affine: per-column scale/shift (or null)
//   CTA tile: 128 rows x 256 cols (both outputs), BK=32, 512 threads.
// ===================================================================
__global__ __launch_bounds__(512, 1) void gemm_dual_tf32(
    const float* __restrict__ A, const float* __restrict__ Wa, const float* __restrict__ Wb,
    float* __restrict__ Ca, float* __restrict__ Cb,
    const float* __restrict__ rowscale,
    const float* __restrict__ affs, const float* __restrict__ affb,
    int M, int K)
{
    __shared__ float As[128 * 32];   // idx = r*32 + (k ^ (4*(r&7)))
    __shared__ float Bs[32 * 256];   // idx = k*256 + (n ^ (8*(k&3)))

    const int tid = threadIdx.x;
    const int lane = tid & 31;
    const int wid = tid >> 5;
    const int wm = wid & 3;          // 4 warps along M (32 rows each)
    const int wn = wid >> 2;         // 4 warps along N (64 cols each)
    const int row0 = blockIdx.x * 128;

    float acc[2][8][4];
#pragma unroll
    for (int i = 0; i < 2; i++)
#pragma unroll
        for (int j = 0; j < 8; j++)
#pragma unroll
            for (int q = 0; q < 4; q++) acc[i][j][q] = 0.f;

    float4 areg[2], breg[4];
    const int iters = K >> 5;

    // ---- global load into regs for tile k0 ----
    auto loadA = [&](int k0) {
#pragma unroll
        for (int i = 0; i < 2; i++) {
            int l = i * 512 + tid;
            int r = l >> 3, kg = l & 7;
            float4 v = make_float4(0.f, 0.f, 0.f, 0.f);
            int grow = row0 + r;
            if (grow < M) {
                v = *(const float4*)(A + (size_t)grow * K + k0 + kg * 4);
                if (affs) {
                    int c = k0 + kg * 4;
                    v.x = v.x * affs[c + 0] + affb[c + 0];
                    v.y = v.y * affs[c + 1] + affb[c + 1];
                    v.z = v.z * affs[c + 2] + affb[c + 2];
                    v.w = v.w * affs[c + 3] + affb[c + 3];
                }
            }
            v.x = to_tf32(v.x); v.y = to_tf32(v.y);
            v.z = to_tf32(v.z); v.w = to_tf32(v.w);
            areg[i] = v;
        }
#pragma unroll
        for (int i = 0; i < 4; i++) {
            int l = i * 512 + tid;
            int k = l >> 6;
            int n4 = (l & 63) * 4;
            const float* src = (n4 < 128) ? (Wa + (size_t)(k0 + k) * 128 + n4)
                                          : (Wb + (size_t)(k0 + k) * 128 + n4 - 128);
            float4 v = *(const float4*)src;
            v.x = to_tf32(v.x); v.y = to_tf32(v.y);
            v.z = to_tf32(v.z); v.w = to_tf32(v.w);
            breg[i] = v;
        }
    };

    loadA(0);

    for (int it = 0; it < iters; ++it) {
        __syncthreads();
        // ---- STS ----
#pragma unroll
        for (int i = 0; i < 2; i++) {
            int l = i * 512 + tid;
            int r = l >> 3, kg = l & 7;
            *(float4*)&As[r * 32 + ((kg * 4) ^ ((r & 7) * 4))] = areg[i];
        }
#pragma unroll
        for (int i = 0; i < 4; i++) {
            int l = i * 512 + tid;
            int k = l >> 6;
            int n4 = (l & 63) * 4;
            *(float4*)&Bs[k * 256 + (n4 ^ ((k & 3) * 8))] = breg[i];
        }
        __syncthreads();

        if (it + 1 < iters) loadA((it + 1) * 32);

        // ---- compute 4 k8 steps ----
#pragma unroll
        for (int kk = 0; kk < 4; kk++) {
            int k8 = kk * 8;
            uint32_t afr[2][4], bfr[8][2];
#pragma unroll
            for (int i = 0; i < 2; i++) {
                int r = wm * 32 + i * 16 + (lane >> 2);
                int c = k8 + (lane & 3);
                int sw = (r & 7) * 4;
                afr[i][0] = __float_as_uint(As[r * 32 + (c ^ sw)]);
                afr[i][1] = __float_as_uint(As[(r + 8) * 32 + (c ^ sw)]);
                afr[i][2] = __float_as_uint(As[r * 32 + ((c + 4) ^ sw)]);
                afr[i][3] = __float_as_uint(As[(r + 8) * 32 + ((c + 4) ^ sw)]);
            }
#pragma unroll
            for (int j = 0; j < 8; j++) {
                int n = wn * 64 + j * 8 + (lane >> 2);
                int k = k8 + (lane & 3);
                int sw = (k & 3) * 8;
                bfr[j][0] = __float_as_uint(Bs[k * 256 + (n ^ sw)]);
                bfr[j][1] = __float_as_uint(Bs[(k + 4) * 256 + (n ^ sw)]);
            }
#pragma unroll
            for (int i = 0; i < 2; i++)
#pragma unroll
                for (int j = 0; j < 8; j++)
                    mma_tf32(acc[i][j], afr[i], bfr[j]);
        }
    }

    // ---- epilogue ----
#pragma unroll
    for (int i = 0; i < 2; i++) {
        int r = row0 + wm * 32 + i * 16 + (lane >> 2);
#pragma unroll
        for (int j = 0; j < 8; j++) {
            int col = wn * 64 + j * 8 + (lane & 3) * 2;
            float* dstm;
            int c;
            if (col < 128) { dstm = Ca; c = col; }
            else           { dstm = Cb; c = col - 128; }
            if (r < M) {
                float s = (col < 128 && rowscale) ? rowscale[r] : 1.f;
                *(float2*)(dstm + (size_t)r * 128 + c) =
                    make_float2(acc[i][j][0] * s, acc[i][j][1] * s);
            }
            if (r + 8 < M) {
                float s = (col < 128 && rowscale) ? rowscale[r + 8] : 1.f;
                *(float2*)(dstm + (size_t)(r + 8) * 128 + c) =
                    make_float2(acc[i][j][2] * s, acc[i][j][3] * s);
            }
        }
    }
}

// -------- GAT attention dot products: el/er per (node, head) --------
__global__ void elr_kernel(const float* __restrict__ f, const float* __restrict__ al,
                           const float* __restrict__ ar, float* __restrict__ el,
                           float* __restrict__ er, int H)
{
    int warp = (blockIdx.x * blockDim.x + threadIdx.x) >> 5;
    if (warp >= NN) return;
    int lane = threadIdx.x & 31;
    float4 fv = ((const float4*)f)[(size_t)warp * 32 + lane];
    float4 a = ((const float4*)al)[lane];
    float4 b = ((const float4*)ar)[lane];
    float pl = fv.x * a.x + fv.y * a.y + fv.z * a.z + fv.w * a.w;
    float pr = fv.x * b.x + fv.y * b.y + fv.z * b.z + fv.w * b.w;
    int L = 32 / H;
    for (int off = L >> 1; off; off >>= 1) {
        pl += __shfl_down_sync(0xffffffffu, pl, off);
        pr += __shfl_down_sync(0xffffffffu, pr, off);
    }
    if ((lane & (L - 1)) == 0) {
        int h = lane / L;
        el[warp * H + h] = pl;
        er[warp * H + h] = pr;
    }
}

// -------- GraphConv scatter: warp per edge --------
__global__ void gc_scatter(const float* __restrict__ xw, const int* __restrict__ src,
                           const int* __restrict__ dst, float* __restrict__ agg)
{
    int e = (blockIdx.x * blockDim.x + threadIdx.x) >> 5;
    if (e >= EIN) return;
    int lane = threadIdx.x & 31;
    int s = src[e], d = dst[e];
    float4 v = ((const float4*)xw)[(size_t)s * 32 + lane];
    red4(agg + (size_t)d * 128 + lane * 4, v.x, v.y, v.z, v.w);
}

// -------- GAT edge softmax passes --------
__global__ void gat_max(const int* __restrict__ src, const int* __restrict__ dst,
                        const float* __restrict__ el, const float* __restrict__ er,
                        float* emax, int H)
{
    int t = blockIdx.x * blockDim.x + threadIdx.x;
    if (t >= ECN * H) return;
    int e = t / H, h = t - e * H;
    int d = dst[e];
    float v = leakyr(el[src[e] * H + h] + er[d * H + h]);
    atomicMaxF(&emax[d * H + h], v);
}

__global__ void gat_exp(const int* __restrict__ src, const int* __restrict__ dst,
                        const float* __restrict__ el, const float* __restrict__ er,
                        const float* __restrict__ emax, float* esum, float* eexp, int H)
{
    int t = blockIdx.x * blockDim.x + threadIdx.x;
    if (t >= ECN * H) return;
    int e = t / H, h = t - e * H;
    int d = dst[e];
    float v = leakyr(el[src[e] * H + h] + er[d * H + h]);
    float ex = __expf(v - emax[d * H + h]);
    eexp[t] = ex;
    atomicAdd(&esum[d * H + h], ex);
}

__global__ void gat_agg(const float* __restrict__ f, const int* __restrict__ src,
                        const int* __restrict__ dst, const float* __restrict__ eexp,
                        const float* __restrict__ esum, float* __restrict__ hc, int H)
{
    int e = (blockIdx.x * blockDim.x + threadIdx.x) >> 5;
    if (e >= ECN) return;
    int lane = threadIdx.x & 31;
    int s = src[e], d = dst[e];
    int h = (lane * H) >> 5;
    float alpha = eexp[e * H + h] / esum[d * H + h];
    float4 v = ((const float4*)f)[(size_t)s * 32 + lane];
    red4(hc + (size_t)d * 128 + lane * 4, alpha * v.x, alpha * v.y, alpha * v.z, alpha * v.w);
}

// layer-3 attention sums over SOURCE nodes
__global__ void att_kernel(const int* __restrict__ src, const int* __restrict__ dst,
                           const float* __restrict__ eexp, const float* __restrict__ esum,
                           float* att)
{
    int e = blockIdx.x * blockDim.x + threadIdx.x;
    if (e >= ECN) return;
    float alpha = eexp[e] / esum[dst[e]];
    atomicAdd(&att[src[e]], alpha);
}

// -------- combine (+ optional leaky) + BN statistics --------
__global__ __launch_bounds__(256) void combine_kernel(
    const float* __restrict__ agg, const float* __restrict__ hc,
    const float* __restrict__ isi, const float* __restrict__ bgc,
    const float* __restrict__ bgat, float* __restrict__ z,
    float* bnsum, float* bnsq, int do_leaky)
{
    __shared__ float ssum[256], ssq[256];
    int tidx = threadIdx.x;
    int stride = gridDim.x * 256;
    float ls = 0.f, lq = 0.f;
    for (int idx = blockIdx.x * 256 + tidx; idx < NN * 128; idx += stride) {
        int n = idx >> 7, ch = idx & 127;
        float v = agg[idx] * isi[n] + bgc[ch] + hc[idx] + bgat[ch];
        if (do_leaky) v = leakyr(v);
        z[idx] = v;
        ls += v;
        lq += v * v;
    }
    ssum[tidx] = ls; ssq[tidx] = lq;
    __syncthreads();
    if (tidx < 128) {
        atomicAdd(&bnsum[tidx], ssum[tidx] + ssum[tidx + 128]);
        atomicAdd(&bnsq[tidx], ssq[tidx] + ssq[tidx + 128]);
    }
}

__global__ void bn_prep(const float* bnsum, const float* bnsq, const float* __restrict__ g,
                        const float* __restrict__ be, float* scale, float* shift)
{
    int c = threadIdx.x;
    if (c >= CC) return;
    float mu = bnsum[c] / (float)NN;
    float var = bnsq[c] / (float)NN - mu * mu;
    float sc = g[c] * rsqrtf(var + 1e-5f);
    scale[c] = sc;
    shift[c] = be[c] - mu * sc;
}

__global__ void bn_apply(const float* __restrict__ z, const float* __restrict__ scale,
                         const float* __restrict__ shift, float* __restrict__ h)
{
    int idx = blockIdx.x * blockDim.x + threadIdx.x;
    if (idx >= NN * 128) return;
    int ch = idx & 127;
    h[idx] = z[idx] * scale[ch] + shift[ch];
}

// -------- pooling --------
__global__ void gcnt_kernel(const int* __restrict__ gid, float* gcnt) {
    int n = blockIdx.x * blockDim.x + threadIdx.x;
    if (n < NN) atomicAdd(&gcnt[gid[n]], 1.f);
}

__global__ void pool_kernel(const float* __restrict__ h, const float* __restrict__ att,
                            const int* __restrict__ gid, float* gsum)
{
    int idx = blockIdx.x * blockDim.x + threadIdx.x;
    if (idx >= NN * 128) return;
    int n = idx >> 7, ch = idx & 127;
    atomicAdd(&gsum[gid[n] * 128 + ch], h[idx] * att[n]);
}

__global__ void out_kernel(const float* __restrict__ gsum, const float* __restrict__ gcnt,
                           const float* __restrict__ att, float* __restrict__ out)
{
    int i = blockIdx.x * blockDim.x + threadIdx.x;
    if (i < GN * 128) {
        out[i] = gsum[i] / fmaxf(gcnt[i >> 7], 1.f);
    } else if (i < GN * 128 + NN) {
        out[i] = att[i - GN * 128];
    }
}

static inline int cdiv(int a, int b) { return (a + b - 1) / b; }

extern "C" void kernel_launch(void* const* d_in, const int* in_sizes, int n_in,
                              void* d_out, int out_size)
{
    (void)in_sizes; (void)n_in; (void)out_size;
    const float* feat = (const float*)d_in[0];
    const int* isrc = (const int*)d_in[1];
    const int* idst = (const int*)d_in[2];
    const int* csrc = (const int*)d_in[3];
    const int* cdst = (const int*)d_in[4];
    const int* gid  = (const int*)d_in[5];
    const float* Wgc[3]  = {(const float*)d_in[6],  (const float*)d_in[12], (const float*)d_in[18]};
    const float* bgc[3]  = {(const float*)d_in[7],  (const float*)d_in[13], (const float*)d_in[19]};
    const float* Wgat[3] = {(const float*)d_in[8],  (const float*)d_in[14], (const float*)d_in[20]};
    const float* al[3]   = {(const float*)d_in[9],  (const float*)d_in[15], (const float*)d_in[21]};
    const float* ar[3]   = {(const float*)d_in[10], (const float*)d_in[16], (const float*)d_in[22]};
    const float* bga[3]  = {(const float*)d_in[11], (const float*)d_in[17], (const float*)d_in[23]};
    const float* gam[3]  = {(const float*)d_in[24], (const float*)d_in[26], (const float*)d_in[28]};
    const float* bet[3]  = {(const float*)d_in[25], (const float*)d_in[27], (const float*)d_in[29]};
    float* out = (float*)d_out;

    float *h, *xw, *f, *agg, *hc, *z, *el, *er, *emax, *esum, *eexp;
    float *iso, *isi, *att, *gsum, *gcnt, *bnsum, *bnsq, *bnscale, *bnshift;
    cudaGetSymbolAddress((void**)&h, g_h);
    cudaGetSymbolAddress((void**)&xw, g_xw);
    cudaGetSymbolAddress((void**)&f, g_f);
    cudaGetSymbolAddress((void**)&agg, g_agg);
    cudaGetSymbolAddress((void**)&hc, g_hc);
    cudaGetSymbolAddress((void**)&z, g_z);
    cudaGetSymbolAddress((void**)&el, g_el);
    cudaGetSymbolAddress((void**)&er, g_er);
    cudaGetSymbolAddress((void**)&emax, g_emax);
    cudaGetSymbolAddress((void**)&esum, g_esum);
    cudaGetSymbolAddress((void**)&eexp, g_eexp);
    cudaGetSymbolAddress((void**)&iso, g_iso);
    cudaGetSymbolAddress((void**)&isi, g_isi);
    cudaGetSymbolAddress((void**)&att, g_att);
    cudaGetSymbolAddress((void**)&gsum, g_gsum);
    cudaGetSymbolAddress((void**)&gcnt, g_gcnt);
    cudaGetSymbolAddress((void**)&bnsum, g_bnsum);
    cudaGetSymbolAddress((void**)&bnsq, g_bnsq);
    cudaGetSymbolAddress((void**)&bnscale, g_bnscale);
    cudaGetSymbolAddress((void**)&bnshift, g_bnshift);

    // ---- degrees (inv-sqrt, clamped to >=1) ----
    fill_kernel<<<cdiv(NN, 256), 256>>>(iso, 0.f, NN);
    fill_kernel<<<cdiv(NN, 256), 256>>>(isi, 0.f, NN);
    deg_kernel<<<cdiv(EIN, 256), 256>>>(isrc, idst, iso, isi);
    invsqrt_kernel<<<cdiv(NN, 256), 256>>>(iso, NN);
    invsqrt_kernel<<<cdiv(NN, 256), 256>>>(isi, NN);

    const int Hs[3] = {4, 4, 1};
    for (int L = 0; L < 3; L++) {
        const float* A = (L == 0) ? feat : z;
        int K = (L == 0) ? FDIM : CC;
        int H = Hs[L];
        const float* affs = (L == 0) ? nullptr : bnscale;
        const float* affb = (L == 0) ? nullptr : bnshift;

        fill_kernel<<<cdiv(NN * CC, 256), 256>>>(agg, 0.f, NN * CC);
        fill_kernel<<<cdiv(NN * CC, 256), 256>>>(hc, 0.f, NN * CC);
        fill_kernel<<<cdiv(NN * H, 256), 256>>>(esum, 0.f, NN * H);
        fill_kernel<<<cdiv(NN * H, 256), 256>>>(emax, -1e30f, NN * H);

        gemm_dual_tf32<<<cdiv(NN, 128), 512>>>(A, Wgc[L], Wgat[L], xw, f,
                                               iso, affs, affb, NN, K);

        fill_kernel<<<1, 128>>>(bnsum, 0.f, CC);
        fill_kernel<<<1, 128>>>(bnsq, 0.f, CC);

        elr_kernel<<<cdiv(NN * 32, 128), 128>>>(f, al[L], ar[L], el, er, H);

        gc_scatter<<<cdiv(EIN * 32, 256), 256>>>(xw, isrc, idst, agg);

        gat_max<<<cdiv(ECN * H, 256), 256>>>(csrc, cdst, el, er, emax, H);
        gat_exp<<<cdiv(ECN * H, 256), 256>>>(csrc, cdst, el, er, emax, esum, eexp, H);
        gat_agg<<<cdiv(ECN * 32, 256), 256>>>(f, csrc, cdst, eexp, esum, hc, H);

        if (L == 2) {
            fill_kernel<<<cdiv(NN, 256), 256>>>(att, 0.f, NN);
            att_kernel<<<cdiv(ECN, 256), 256>>>(csrc, cdst, eexp, esum, att);
        }

        combine_kernel<<<2048, 256>>>(agg, hc, isi, bgc[L], bga[L], z, bnsum, bnsq, (L < 2) ? 1 : 0);
        bn_prep<<<1, 128>>>(bnsum, bnsq, gam[L], bet[L], bnscale, bnshift);
        if (L == 2)
            bn_apply<<<cdiv(NN * CC, 256), 256>>>(z, bnscale, bnshift, h);
    }

    // ---- pooling ----
    fill_kernel<<<cdiv(GN * CC, 256), 256>>>(gsum, 0.f, GN * CC);
    fill_kernel<<<cdiv(GN, 256), 256>>>(gcnt, 0.f, GN);
    gcnt_kernel<<<cdiv(NN, 256), 256>>>(gid, gcnt);
    pool_kernel<<<cdiv(NN * CC, 256), 256>>>(h, att, gid, gsum);
    out_kernel<<<cdiv(GN * CC + NN, 256), 256>>>(gsum, gcnt, att, out);
}

// round 4
// speedup vs baseline: 3.2291x; 1.2010x over previous
#include <cuda_runtime.h>
#include <cstdint>

#define NN  100000
#define EIN 1600000
#define ECN 800000
#define GN  2000
#define FDIM 512
#define CC  128

// -------- scratch (device globals; no allocation) --------
__device__ float g_h[NN*CC];
__device__ float g_xw[NN*CC];
__device__ float g_f[NN*CC];
__device__ float g_z[NN*CC];
__device__ float g_el[NN*4];
__device__ float g_er[NN*4];
__device__ float g_alpha[ECN*4];
__device__ float g_iso[NN];
__device__ float g_isi[NN];
__device__ float g_att[NN];
__device__ float g_gsum[GN*CC];
__device__ float g_gcnt[GN];
__device__ float g_bnsum[CC];
__device__ float g_bnsq[CC];
__device__ float g_bnscale[CC];
__device__ float g_bnshift[CC];
// CSR scratch
__device__ int g_idegi[NN];
__device__ int g_idegc[NN];
__device__ int g_rpi[NN];
__device__ int g_rpc[NN];
__device__ int g_cur[NN];
__device__ int g_bsum[512];
__device__ int g_ci[EIN];
__device__ int g_ccol[ECN];

__device__ __forceinline__ float leakyr(float x) { return x >= 0.f ? x : 0.2f * x; }

__device__ __forceinline__ float to_tf32(float x) {
    float r;
    asm("cvt.rna.tf32.f32 %0, %1;" : "=f"(r) : "f"(x));
    return r;
}

__device__ __forceinline__ void mma_tf32(float* d, const uint32_t* a, const uint32_t* b) {
    asm volatile(
        "mma.sync.aligned.m16n8k8.row.col.f32.tf32.tf32.f32 "
        "{%0,%1,%2,%3}, {%4,%5,%6,%7}, {%8,%9}, {%0,%1,%2,%3};"
        : "+f"(d[0]), "+f"(d[1]), "+f"(d[2]), "+f"(d[3])
        : "r"(a[0]), "r"(a[1]), "r"(a[2]), "r"(a[3]), "r"(b[0]), "r"(b[1]));
}

// -------- utility --------
__global__ void fill_kernel(float* p, float v, int n) {
    int i = blockIdx.x * blockDim.x + threadIdx.x;
    if (i < n) p[i] = v;
}
__global__ void filli_kernel(int* p, int v, int n) {
    int i = blockIdx.x * blockDim.x + threadIdx.x;
    if (i < n) p[i] = v;
}
__global__ void copyi_kernel(int* d, const int* s, int n) {
    int i = blockIdx.x * blockDim.x + threadIdx.x;
    if (i < n) d[i] = s[i];
}

// degree: float out-degree of src (inter), int in-degree of dst
__global__ void deg_inter(const int* __restrict__ src, const int* __restrict__ dst,
                          float* iso, int* idegi) {
    int e = blockIdx.x * blockDim.x + threadIdx.x;
    if (e >= EIN) return;
    atomicAdd(&iso[src[e]], 1.f);
    atomicAdd(&idegi[dst[e]], 1);
}
__global__ void deg_cross(const int* __restrict__ dst, int* idegc) {
    int e = blockIdx.x * blockDim.x + threadIdx.x;
    if (e >= ECN) return;
    atomicAdd(&idegc[dst[e]], 1);
}
__global__ void invsqrt_kernel(float* p, int n) {
    int i = blockIdx.x * blockDim.x + threadIdx.x;
    if (i < n) p[i] = rsqrtf(fmaxf(p[i], 1.f));
}
__global__ void isi_from_ideg(const int* __restrict__ ideg, float* isi, int n) {
    int i = blockIdx.x * blockDim.x + threadIdx.x;
    if (i < n) isi[i] = rsqrtf(fmaxf((float)ideg[i], 1.f));
}

// -------- 3-stage exclusive scan over n ints --------
__global__ void scan1(const int* __restrict__ in, int* out, int* bsum, int n) {
    __shared__ int sh[256];
    int i = blockIdx.x * 256 + threadIdx.x;
    int v = (i < n) ? in[i] : 0;
    sh[threadIdx.x] = v;
    __syncthreads();
    for (int off = 1; off < 256; off <<= 1) {
        int t = (threadIdx.x >= off) ? sh[threadIdx.x - off] : 0;
        __syncthreads();
        sh[threadIdx.x] += t;
        __syncthreads();
    }
    if (i < n) out[i] = sh[threadIdx.x] - v;   // exclusive
    if (threadIdx.x == 255) bsum[blockIdx.x] = sh[255];
}
__global__ void scan2(int* bsum, int nb) {
    __shared__ int sh[512];
    int t = threadIdx.x;
    int v = (t < nb) ? bsum[t] : 0;
    sh[t] = v;
    __syncthreads();
    for (int off = 1; off < 512; off <<= 1) {
        int x = (t >= off) ? sh[t - off] : 0;
        __syncthreads();
        sh[t] += x;
        __syncthreads();
    }
    if (t < nb) bsum[t] = sh[t] - v;           // exclusive
}
__global__ void scan3(int* out, const int* __restrict__ bsum, int n) {
    int i = blockIdx.x * 256 + threadIdx.x;
    if (i < n) out[i] += bsum[blockIdx.x];
}

__global__ void csr_scatter(const int* __restrict__ src, const int* __restrict__ dst,
                            int* cur, int* col, int E) {
    int e = blockIdx.x * blockDim.x + threadIdx.x;
    if (e >= E) return;
    int p = atomicAdd(&cur[dst[e]], 1);
    col[p] = src[e];
}

// ===================================================================
// Fused dual-GEMM (tf32 tensor core), CTA 128x256, BK=32, 512 thr
// ===================================================================
__global__ __launch_bounds__(512, 1) void gemm_dual_tf32(
    const float* __restrict__ A, const float* __restrict__ Wa, const float* __restrict__ Wb,
    float* __restrict__ Ca, float* __restrict__ Cb,
    const float* __restrict__ rowscale,
    const float* __restrict__ affs, const float* __restrict__ affb,
    int M, int K)
{
    __shared__ float As[128 * 32];
    __shared__ float Bs[32 * 256];

    const int tid = threadIdx.x;
    const int lane = tid & 31;
    const int wid = tid >> 5;
    const int wm = wid & 3;
    const int wn = wid >> 2;
    const int row0 = blockIdx.x * 128;

    float acc[2][8][4];
#pragma unroll
    for (int i = 0; i < 2; i++)
#pragma unroll
        for (int j = 0; j < 8; j++)
#pragma unroll
            for (int q = 0; q < 4; q++) acc[i][j][q] = 0.f;

    float4 areg[2], breg[4];
    const int iters = K >> 5;

    auto loadA = [&](int k0) {
#pragma unroll
        for (int i = 0; i < 2; i++) {
            int l = i * 512 + tid;
            int r = l >> 3, kg = l & 7;
            float4 v = make_float4(0.f, 0.f, 0.f, 0.f);
            int grow = row0 + r;
            if (grow < M) {
                v = *(const float4*)(A + (size_t)grow * K + k0 + kg * 4);
                if (affs) {
                    int c = k0 + kg * 4;
                    v.x = v.x * affs[c + 0] + affb[c + 0];
                    v.y = v.y * affs[c + 1] + affb[c + 1];
                    v.z = v.z * affs[c + 2] + affb[c + 2];
                    v.w = v.w * affs[c + 3] + affb[c + 3];
                }
            }
            v.x = to_tf32(v.x); v.y = to_tf32(v.y);
            v.z = to_tf32(v.z); v.w = to_tf32(v.w);
            areg[i] = v;
        }
#pragma unroll
        for (int i = 0; i < 4; i++) {
            int l = i * 512 + tid;
            int k = l >> 6;
            int n4 = (l & 63) * 4;
            const float* srcp = (n4 < 128) ? (Wa + (size_t)(k0 + k) * 128 + n4)
                                           : (Wb + (size_t)(k0 + k) * 128 + n4 - 128);
            float4 v = *(const float4*)srcp;
            v.x = to_tf32(v.x); v.y = to_tf32(v.y);
            v.z = to_tf32(v.z); v.w = to_tf32(v.w);
            breg[i] = v;
        }
    };

    loadA(0);

    for (int it = 0; it < iters; ++it) {
        __syncthreads();
#pragma unroll
        for (int i = 0; i < 2; i++) {
            int l = i * 512 + tid;
            int r = l >> 3, kg = l & 7;
            *(float4*)&As[r * 32 + ((kg * 4) ^ ((r & 7) * 4))] = areg[i];
        }
#pragma unroll
        for (int i = 0; i < 4; i++) {
            int l = i * 512 + tid;
            int k = l >> 6;
            int n4 = (l & 63) * 4;
            *(float4*)&Bs[k * 256 + (n4 ^ ((k & 3) * 8))] = breg[i];
        }
        __syncthreads();

        if (it + 1 < iters) loadA((it + 1) * 32);

#pragma unroll
        for (int kk = 0; kk < 4; kk++) {
            int k8 = kk * 8;
            uint32_t afr[2][4], bfr[8][2];
#pragma unroll
            for (int i = 0; i < 2; i++) {
                int r = wm * 32 + i * 16 + (lane >> 2);
                int c = k8 + (lane & 3);
                int sw = (r & 7) * 4;
                afr[i][0] = __float_as_uint(As[r * 32 + (c ^ sw)]);
                afr[i][1] = __float_as_uint(As[(r + 8) * 32 + (c ^ sw)]);
                afr[i][2] = __float_as_uint(As[r * 32 + ((c + 4) ^ sw)]);
                afr[i][3] = __float_as_uint(As[(r + 8) * 32 + ((c + 4) ^ sw)]);
            }
#pragma unroll
            for (int j = 0; j < 8; j++) {
                int n = wn * 64 + j * 8 + (lane >> 2);
                int k = k8 + (lane & 3);
                int sw = (k & 3) * 8;
                bfr[j][0] = __float_as_uint(Bs[k * 256 + (n ^ sw)]);
                bfr[j][1] = __float_as_uint(Bs[(k + 4) * 256 + (n ^ sw)]);
            }
#pragma unroll
            for (int i = 0; i < 2; i++)
#pragma unroll
                for (int j = 0; j < 8; j++)
                    mma_tf32(acc[i][j], afr[i], bfr[j]);
        }
    }

#pragma unroll
    for (int i = 0; i < 2; i++) {
        int r = row0 + wm * 32 + i * 16 + (lane >> 2);
#pragma unroll
        for (int j = 0; j < 8; j++) {
            int col = wn * 64 + j * 8 + (lane & 3) * 2;
            float* dstm;
            int c;
            if (col < 128) { dstm = Ca; c = col; }
            else           { dstm = Cb; c = col - 128; }
            if (r < M) {
                float s = (col < 128 && rowscale) ? rowscale[r] : 1.f;
                *(float2*)(dstm + (size_t)r * 128 + c) =
                    make_float2(acc[i][j][0] * s, acc[i][j][1] * s);
            }
            if (r + 8 < M) {
                float s = (col < 128 && rowscale) ? rowscale[r + 8] : 1.f;
                *(float2*)(dstm + (size_t)(r + 8) * 128 + c) =
                    make_float2(acc[i][j][2] * s, acc[i][j][3] * s);
            }
        }
    }
}

// -------- GAT attention dot products --------
__global__ void elr_kernel(const float* __restrict__ f, const float* __restrict__ al,
                           const float* __restrict__ ar, float* __restrict__ el,
                           float* __restrict__ er, int H)
{
    int warp = (blockIdx.x * blockDim.x + threadIdx.x) >> 5;
    if (warp >= NN) return;
    int lane = threadIdx.x & 31;
    float4 fv = ((const float4*)f)[(size_t)warp * 32 + lane];
    float4 a = ((const float4*)al)[lane];
    float4 b = ((const float4*)ar)[lane];
    float pl = fv.x * a.x + fv.y * a.y + fv.z * a.z + fv.w * a.w;
    float pr = fv.x * b.x + fv.y * b.y + fv.z * b.z + fv.w * b.w;
    int L = 32 / H;
    for (int off = L >> 1; off; off >>= 1) {
        pl += __shfl_down_sync(0xffffffffu, pl, off);
        pr += __shfl_down_sync(0xffffffffu, pr, off);
    }
    if ((lane & (L - 1)) == 0) {
        int h = lane / L;
        el[warp * H + h] = pl;
        er[warp * H + h] = pr;
    }
}

// -------- per-node softmax: computes alpha in CSR slot order --------
// block = 128 (4 warps); warp w handles head w (H=4) or warp 0 only (H=1)
template<int H>
__global__ __launch_bounds__(128) void gat_ms_alpha(
    const float* __restrict__ el, const float* __restrict__ er,
    const int* __restrict__ rpc, const int* __restrict__ degc,
    const int* __restrict__ ccol, float* __restrict__ alpha)
{
    int n = blockIdx.x;
    int wid = threadIdx.x >> 5;
    int lane = threadIdx.x & 31;
    if (H == 1 && wid > 0) return;
    int h = (H == 1) ? 0 : wid;
    float ern = __ldg(er + n * H + h);
    int c0 = __ldg(rpc + n), deg = __ldg(degc + n);
    if (deg == 0) return;
    int cend = c0 + deg;
    // pass 1: online (max, sum)
    float m = -1e30f, s = 0.f;
    for (int j = c0 + lane; j < cend; j += 32) {
        int sn = __ldg(ccol + j);
        float e = leakyr(__ldg(el + sn * H + h) + ern);
        if (e > m) { s *= __expf(m - e); m = e; }
        s += __expf(e - m);
    }
#pragma unroll
    for (int off = 16; off; off >>= 1) {
        float m2 = __shfl_xor_sync(0xffffffffu, m, off);
        float s2 = __shfl_xor_sync(0xffffffffu, s, off);
        float mm = fmaxf(m, m2);
        s = s * __expf(m - mm) + s2 * __expf(m2 - mm);
        m = mm;
    }
    // pass 2: write alpha at CSR slots (all lanes have m, s)
    float inv = 1.f / s;
    for (int j = c0 + lane; j < cend; j += 32) {
        int sn = __ldg(ccol + j);
        float e = leakyr(__ldg(el + sn * H + h) + ern);
        alpha[(size_t)j * H + h] = __expf(e - m) * inv;
    }
}

// layer-3 attention sums over SOURCE nodes (CSR slot order; ccol = src)
__global__ void att_kernel(const int* __restrict__ ccol, const float* __restrict__ alpha,
                           float* att)
{
    int j = blockIdx.x * blockDim.x + threadIdx.x;
    if (j >= ECN) return;
    atomicAdd(&att[ccol[j]], alpha[j]);
}

// ===================================================================
// Fused layer: per-node gather (GraphConv + GAT) + combine + BN stats
// ===================================================================
template<int H, int DO_LEAKY>
__global__ __launch_bounds__(128) void layer_fused(
    const float* __restrict__ xw, const float* __restrict__ f,
    const float* __restrict__ alpha, const float* __restrict__ isi,
    const int* __restrict__ rpi, const int* __restrict__ degi, const int* __restrict__ ci,
    const int* __restrict__ rpc, const int* __restrict__ degc, const int* __restrict__ ccol,
    const float* __restrict__ bgc, const float* __restrict__ bga,
    float* __restrict__ z, float* __restrict__ bnsum, float* __restrict__ bnsq)
{
    const int ch = threadIdx.x;
    const int h = (H == 1) ? 0 : (ch >> 5);
    const float bc = __ldg(bgc + ch) + __ldg(bga + ch);
    float ls = 0.f, lq = 0.f;

    for (int n = blockIdx.x; n < NN; n += gridDim.x) {
        // GraphConv gather
        float a = 0.f;
        int j = __ldg(rpi + n);
        int bend = j + __ldg(degi + n);
        for (; j + 4 <= bend; j += 4) {
            int s0 = __ldg(ci + j), s1 = __ldg(ci + j + 1);
            int s2 = __ldg(ci + j + 2), s3 = __ldg(ci + j + 3);
            float v0 = __ldg(xw + (size_t)s0 * 128 + ch);
            float v1 = __ldg(xw + (size_t)s1 * 128 + ch);
            float v2 = __ldg(xw + (size_t)s2 * 128 + ch);
            float v3 = __ldg(xw + (size_t)s3 * 128 + ch);
            a += (v0 + v1) + (v2 + v3);
        }
        for (; j < bend; j++)
            a += __ldg(xw + (size_t)__ldg(ci + j) * 128 + ch);

        // GAT gather with CSR-ordered alpha
        float g = 0.f;
        int k = __ldg(rpc + n);
        int cend = k + __ldg(degc + n);
        for (; k + 4 <= cend; k += 4) {
            int s0 = __ldg(ccol + k), s1 = __ldg(ccol + k + 1);
            int s2 = __ldg(ccol + k + 2), s3 = __ldg(ccol + k + 3);
            float a0 = __ldg(alpha + (size_t)(k + 0) * H + h);
            float a1 = __ldg(alpha + (size_t)(k + 1) * H + h);
            float a2 = __ldg(alpha + (size_t)(k + 2) * H + h);
            float a3 = __ldg(alpha + (size_t)(k + 3) * H + h);
            float v0 = __ldg(f + (size_t)s0 * 128 + ch);
            float v1 = __ldg(f + (size_t)s1 * 128 + ch);
            float v2 = __ldg(f + (size_t)s2 * 128 + ch);
            float v3 = __ldg(f + (size_t)s3 * 128 + ch);
            g += a0 * v0 + a1 * v1 + a2 * v2 + a3 * v3;
        }
        for (; k < cend; k++) {
            int s0 = __ldg(ccol + k);
            g += __ldg(alpha + (size_t)k * H + h) * __ldg(f + (size_t)s0 * 128 + ch);
        }

        float v = a * __ldg(isi + n) + g + bc;
        if (DO_LEAKY) v = leakyr(v);
        z[(size_t)n * 128 + ch] = v;
        ls += v;
        lq += v * v;
    }
    atomicAdd(&bnsum[ch], ls);
    atomicAdd(&bnsq[ch], lq);
}

__global__ void bn_prep(const float* bnsum, const float* bnsq, const float* __restrict__ g,
                        const float* __restrict__ be, float* scale, float* shift)
{
    int c = threadIdx.x;
    if (c >= CC) return;
    float mu = bnsum[c] / (float)NN;
    float var = bnsq[c] / (float)NN - mu * mu;
    float sc = g[c] * rsqrtf(var + 1e-5f);
    scale[c] = sc;
    shift[c] = be[c] - mu * sc;
}

__global__ void bn_apply(const float* __restrict__ z, const float* __restrict__ scale,
                         const float* __restrict__ shift, float* __restrict__ h)
{
    int idx = blockIdx.x * blockDim.x + threadIdx.x;
    if (idx >= NN * 128) return;
    int ch = idx & 127;
    h[idx] = z[idx] * scale[ch] + shift[ch];
}

// -------- pooling --------
__global__ void gcnt_kernel(const int* __restrict__ gid, float* gcnt) {
    int n = blockIdx.x * blockDim.x + threadIdx.x;
    if (n < NN) atomicAdd(&gcnt[gid[n]], 1.f);
}
__global__ void pool_kernel(const float* __restrict__ h, const float* __restrict__ att,
                            const int* __restrict__ gid, float* gsum)
{
    int idx = blockIdx.x * blockDim.x + threadIdx.x;
    if (idx >= NN * 128) return;
    int n = idx >> 7, ch = idx & 127;
    atomicAdd(&gsum[gid[n] * 128 + ch], h[idx] * att[n]);
}
__global__ void out_kernel(const float* __restrict__ gsum, const float* __restrict__ gcnt,
                           const float* __restrict__ att, float* __restrict__ out)
{
    int i = blockIdx.x * blockDim.x + threadIdx.x;
    if (i < GN * 128) {
        out[i] = gsum[i] / fmaxf(gcnt[i >> 7], 1.f);
    } else if (i < GN * 128 + NN) {
        out[i] = att[i - GN * 128];
    }
}

static inline int cdiv(int a, int b) { return (a + b - 1) / b; }

extern "C" void kernel_launch(void* const* d_in, const int* in_sizes, int n_in,
                              void* d_out, int out_size)
{
    (void)in_sizes; (void)n_in; (void)out_size;
    const float* feat = (const float*)d_in[0];
    const int* isrc = (const int*)d_in[1];
    const int* idst = (const int*)d_in[2];
    const int* csrc = (const int*)d_in[3];
    const int* cdst = (const int*)d_in[4];
    const int* gid  = (const int*)d_in[5];
    const float* Wgc[3]  = {(const float*)d_in[6],  (const float*)d_in[12], (const float*)d_in[18]};
    const float* bgc[3]  = {(const float*)d_in[7],  (const float*)d_in[13], (const float*)d_in[19]};
    const float* Wgat[3] = {(const float*)d_in[8],  (const float*)d_in[14], (const float*)d_in[20]};
    const float* al[3]   = {(const float*)d_in[9],  (const float*)d_in[15], (const float*)d_in[21]};
    const float* ar[3]   = {(const float*)d_in[10], (const float*)d_in[16], (const float*)d_in[22]};
    const float* bga[3]  = {(const float*)d_in[11], (const float*)d_in[17], (const float*)d_in[23]};
    const float* gam[3]  = {(const float*)d_in[24], (const float*)d_in[26], (const float*)d_in[28]};
    const float* bet[3]  = {(const float*)d_in[25], (const float*)d_in[27], (const float*)d_in[29]};
    float* out = (float*)d_out;

    float *h, *xw, *f, *z, *el, *er, *alpha;
    float *iso, *isi, *att, *gsum, *gcnt, *bnsum, *bnsq, *bnscale, *bnshift;
    int *idegi, *idegc, *rpi, *rpc, *cur, *bsum, *ci, *ccol;
    cudaGetSymbolAddress((void**)&h, g_h);
    cudaGetSymbolAddress((void**)&xw, g_xw);
    cudaGetSymbolAddress((void**)&f, g_f);
    cudaGetSymbolAddress((void**)&z, g_z);
    cudaGetSymbolAddress((void**)&el, g_el);
    cudaGetSymbolAddress((void**)&er, g_er);
    cudaGetSymbolAddress((void**)&alpha, g_alpha);
    cudaGetSymbolAddress((void**)&iso, g_iso);
    cudaGetSymbolAddress((void**)&isi, g_isi);
    cudaGetSymbolAddress((void**)&att, g_att);
    cudaGetSymbolAddress((void**)&gsum, g_gsum);
    cudaGetSymbolAddress((void**)&gcnt, g_gcnt);
    cudaGetSymbolAddress((void**)&bnsum, g_bnsum);
    cudaGetSymbolAddress((void**)&bnsq, g_bnsq);
    cudaGetSymbolAddress((void**)&bnscale, g_bnscale);
    cudaGetSymbolAddress((void**)&bnshift, g_bnshift);
    cudaGetSymbolAddress((void**)&idegi, g_idegi);
    cudaGetSymbolAddress((void**)&idegc, g_idegc);
    cudaGetSymbolAddress((void**)&rpi, g_rpi);
    cudaGetSymbolAddress((void**)&rpc, g_rpc);
    cudaGetSymbolAddress((void**)&cur, g_cur);
    cudaGetSymbolAddress((void**)&bsum, g_bsum);
    cudaGetSymbolAddress((void**)&ci, g_ci);
    cudaGetSymbolAddress((void**)&ccol, g_ccol);

    const int NB = cdiv(NN, 256);   // 391 scan blocks (<=512)

    // ---- degrees ----
    fill_kernel<<<cdiv(NN, 256), 256>>>(iso, 0.f, NN);
    filli_kernel<<<cdiv(NN, 256), 256>>>(idegi, 0, NN);
    filli_kernel<<<cdiv(NN, 256), 256>>>(idegc, 0, NN);
    deg_inter<<<cdiv(EIN, 256), 256>>>(isrc, idst, iso, idegi);
    deg_cross<<<cdiv(ECN, 256), 256>>>(cdst, idegc);
    invsqrt_kernel<<<cdiv(NN, 256), 256>>>(iso, NN);
    isi_from_ideg<<<cdiv(NN, 256), 256>>>(idegi, isi, NN);

    // ---- CSR build (inter) ----
    scan1<<<NB, 256>>>(idegi, rpi, bsum, NN);
    scan2<<<1, 512>>>(bsum, NB);
    scan3<<<NB, 256>>>(rpi, bsum, NN);
    copyi_kernel<<<cdiv(NN, 256), 256>>>(cur, rpi, NN);
    csr_scatter<<<cdiv(EIN, 256), 256>>>(isrc, idst, cur, ci, EIN);
    // ---- CSR build (cross) ----
    scan1<<<NB, 256>>>(idegc, rpc, bsum, NN);
    scan2<<<1, 512>>>(bsum, NB);
    scan3<<<NB, 256>>>(rpc, bsum, NN);
    copyi_kernel<<<cdiv(NN, 256), 256>>>(cur, rpc, NN);
    csr_scatter<<<cdiv(ECN, 256), 256>>>(csrc, cdst, cur, ccol, ECN);

    const int Hs[3] = {4, 4, 1};
    for (int L = 0; L < 3; L++) {
        const float* A = (L == 0) ? feat : z;
        int K = (L == 0) ? FDIM : CC;
        int H = Hs[L];
        const float* affs = (L == 0) ? nullptr : bnscale;
        const float* affb = (L == 0) ? nullptr : bnshift;

        gemm_dual_tf32<<<cdiv(NN, 128), 512>>>(A, Wgc[L], Wgat[L], xw, f,
                                               iso, affs, affb, NN, K);

        fill_kernel<<<1, 128>>>(bnsum, 0.f, CC);
        fill_kernel<<<1, 128>>>(bnsq, 0.f, CC);

        elr_kernel<<<cdiv(NN * 32, 128), 128>>>(f, al[L], ar[L], el, er, H);

        if (H == 4)
            gat_ms_alpha<4><<<NN, 128>>>(el, er, rpc, idegc, ccol, alpha);
        else
            gat_ms_alpha<1><<<NN, 128>>>(el, er, rpc, idegc, ccol, alpha);

        if (L == 2) {
            fill_kernel<<<cdiv(NN, 256), 256>>>(att, 0.f, NN);
            att_kernel<<<cdiv(ECN, 256), 256>>>(ccol, alpha, att);
        }

        if (L < 2)
            layer_fused<4, 1><<<2048, 128>>>(xw, f, alpha, isi, rpi, idegi, ci,
                                             rpc, idegc, ccol, bgc[L], bga[L],
                                             z, bnsum, bnsq);
        else
            layer_fused<1, 0><<<2048, 128>>>(xw, f, alpha, isi, rpi, idegi, ci,
                                             rpc, idegc, ccol, bgc[L], bga[L],
                                             z, bnsum, bnsq);

        bn_prep<<<1, 128>>>(bnsum, bnsq, gam[L], bet[L], bnscale, bnshift);
        if (L == 2)
            bn_apply<<<cdiv(NN * CC, 256), 256>>>(z, bnscale, bnshift, h);
    }

    // ---- pooling ----
    fill_kernel<<<cdiv(GN * CC, 256), 256>>>(gsum, 0.f, GN * CC);
    fill_kernel<<<cdiv(GN, 256), 256>>>(gcnt, 0.f, GN);
    gcnt_kernel<<<cdiv(NN, 256), 256>>>(gid, gcnt);
    pool_kernel<<<cdiv(NN * CC, 256), 256>>>(h, att, gid, gsum);
    out_kernel<<<cdiv(GN * CC + NN, 256), 256>>>(gsum, gcnt, att, out);
}